// round 2
// baseline (speedup 1.0000x reference)
#include <cuda_runtime.h>
#include <math.h>

#define Bn 4
#define Nn 512
#define Cc 256
#define Hh 8
#define Dd 32
#define DG 6
#define HID 16

// ---------------- scratch (device globals; no allocation) ----------------
__device__ float g_Q[Bn * Nn * Cc];
__device__ float g_K[Bn * Nn * Cc];
__device__ float g_V[Bn * Nn * Cc];
__device__ float g_O[Bn * Nn * Cc];
__device__ float g_pre[(size_t)Bn * Hh * Nn * Nn];   // [b][h][n][m]

__device__ __forceinline__ float swishf(float x) {
    float e = __expf(-x);
    return x * __fdividef(1.0f, 1.0f + e);
}

// ---------------- generic GEMM: Y = X(MxK) @ W(KxN) + bias ----------------
// BM=64, BN=64, BK=16, 256 threads, 4x4 microtile
__global__ void gemm_bias_kernel(const float* __restrict__ X,
                                 const float* __restrict__ W,
                                 const float* __restrict__ bias,
                                 float* __restrict__ Y,
                                 int M, int Ncols, int K) {
    __shared__ float As[16][68];   // As[k][m], padded
    __shared__ float Bs[16][68];   // Bs[k][n], padded

    int t  = threadIdx.x;
    int tx = t & 15;
    int ty = t >> 4;
    int m0 = blockIdx.y * 64;
    int n0 = blockIdx.x * 64;

    float acc[4][4];
#pragma unroll
    for (int i = 0; i < 4; i++)
#pragma unroll
        for (int j = 0; j < 4; j++) acc[i][j] = 0.0f;

    for (int k0 = 0; k0 < K; k0 += 16) {
        // load X tile 64x16 (transposed into As)
        {
            int r = t >> 2;            // 0..63
            int c = (t & 3) << 2;      // 0,4,8,12
            float4 v = *(const float4*)&X[(size_t)(m0 + r) * K + k0 + c];
            As[c + 0][r] = v.x;
            As[c + 1][r] = v.y;
            As[c + 2][r] = v.z;
            As[c + 3][r] = v.w;
        }
        // load W tile 16x64
        {
            int r = t >> 4;            // 0..15
            int c = (t & 15) << 2;     // 0..60
            *(float4*)&Bs[r][c] = *(const float4*)&W[(size_t)(k0 + r) * Ncols + n0 + c];
        }
        __syncthreads();
#pragma unroll
        for (int k = 0; k < 16; k++) {
            float a[4], b[4];
            *(float4*)a = *(const float4*)&As[k][ty << 2];
            *(float4*)b = *(const float4*)&Bs[k][tx << 2];
#pragma unroll
            for (int i = 0; i < 4; i++)
#pragma unroll
                for (int j = 0; j < 4; j++) acc[i][j] = fmaf(a[i], b[j], acc[i][j]);
        }
        __syncthreads();
    }

    float4 bv = *(const float4*)&bias[n0 + (tx << 2)];
#pragma unroll
    for (int i = 0; i < 4; i++) {
        float4 o;
        o.x = acc[i][0] + bv.x;
        o.y = acc[i][1] + bv.y;
        o.z = acc[i][2] + bv.z;
        o.w = acc[i][3] + bv.w;
        *(float4*)&Y[(size_t)(m0 + (ty << 2) + i) * Ncols + n0 + (tx << 2)] = o;
    }
}

// ---------------- logits: pre[b][h][n][m] = A_loc + A_feat ----------------
// Tile: 16 n x 16 m per CTA, 256 threads, one (n,m) pair per thread.
__global__ void logits_kernel(const float* __restrict__ g,
                              const float* __restrict__ Q,
                              const float* __restrict__ K,
                              const float* __restrict__ w1, const float* __restrict__ b1,
                              const float* __restrict__ w2, const float* __restrict__ b2,
                              const float* __restrict__ w3, const float* __restrict__ b3,
                              float* __restrict__ pre) {
    __shared__ float Qs[16][260];
    __shared__ float Ks[16][260];
    __shared__ float w1s[Hh][DG][HID];
    __shared__ float b1s[Hh][HID];
    __shared__ float w2s[Hh][HID][HID];
    __shared__ float b2s[Hh][HID];
    __shared__ float w3s[Hh][HID];
    __shared__ float b3s[Hh];

    int b  = blockIdx.z;
    int n0 = blockIdx.y * 16;
    int m0 = blockIdx.x * 16;
    int t  = threadIdx.x;

    // cooperative weight loads
    for (int i = t; i < Hh * DG * HID; i += 256) ((float*)w1s)[i] = w1[i];
    for (int i = t; i < Hh * HID; i += 256)      ((float*)b1s)[i] = b1[i];
    for (int i = t; i < Hh * HID * HID; i += 256)((float*)w2s)[i] = w2[i];
    for (int i = t; i < Hh * HID; i += 256)      ((float*)b2s)[i] = b2[i];
    if (t < Hh * HID) ((float*)w3s)[t] = w3[t];
    if (t < Hh)       b3s[t] = b3[t];

    // Q/K tiles: 16 rows x 256 cols each
    {
        int r = t >> 4;
        int c = (t & 15) << 4;   // 16 floats per thread
        const float* qsrc = Q + (size_t)(b * Nn + n0 + r) * Cc + c;
        const float* ksrc = K + (size_t)(b * Nn + m0 + r) * Cc + c;
#pragma unroll
        for (int v = 0; v < 4; v++) {
            *(float4*)&Qs[r][c + v * 4] = *(const float4*)(qsrc + v * 4);
            *(float4*)&Ks[r][c + v * 4] = *(const float4*)(ksrc + v * 4);
        }
    }
    __syncthreads();

    int ni = t >> 4;
    int mi = t & 15;
    int n  = n0 + ni;
    int m  = m0 + mi;

    // pairwise_g[b][n][m][0..5]  (24B, 8B aligned)
    float gv[DG];
    {
        const float* gp = g + ((size_t)(b * Nn + n) * Nn + m) * DG;
        float2 g0 = *(const float2*)(gp + 0);
        float2 g1 = *(const float2*)(gp + 2);
        float2 g2 = *(const float2*)(gp + 4);
        gv[0] = g0.x; gv[1] = g0.y; gv[2] = g1.x;
        gv[3] = g1.y; gv[4] = g2.x; gv[5] = g2.y;
    }

    const float inv_sqrt_c = 0.0625f;   // 1/sqrt(256)

#pragma unroll 1
    for (int h = 0; h < Hh; h++) {
        // ----- A_feat: dot over this head's 32 channels -----
        float af = 0.0f;
#pragma unroll
        for (int kk = 0; kk < 8; kk++) {
            float4 q4 = *(const float4*)&Qs[ni][h * 32 + kk * 4];
            float4 k4 = *(const float4*)&Ks[mi][h * 32 + kk * 4];
            af = fmaf(q4.x, k4.x, af);
            af = fmaf(q4.y, k4.y, af);
            af = fmaf(q4.z, k4.z, af);
            af = fmaf(q4.w, k4.w, af);
        }

        // ----- layer 1: 6 -> 16 + swish -----
        float x1[HID];
#pragma unroll
        for (int j = 0; j < HID; j += 4) {
            float4 a = *(const float4*)&b1s[h][j];
#pragma unroll
            for (int k = 0; k < DG; k++) {
                float4 w = *(const float4*)&w1s[h][k][j];
                a.x = fmaf(gv[k], w.x, a.x);
                a.y = fmaf(gv[k], w.y, a.y);
                a.z = fmaf(gv[k], w.z, a.z);
                a.w = fmaf(gv[k], w.w, a.w);
            }
            x1[j + 0] = swishf(a.x);
            x1[j + 1] = swishf(a.y);
            x1[j + 2] = swishf(a.z);
            x1[j + 3] = swishf(a.w);
        }

        // ----- layer 2: 16 -> 16 + swish -----
        float x2[HID];
#pragma unroll
        for (int j = 0; j < HID; j += 4) {
            float4 a = *(const float4*)&b2s[h][j];
#pragma unroll
            for (int k = 0; k < HID; k++) {
                float4 w = *(const float4*)&w2s[h][k][j];
                a.x = fmaf(x1[k], w.x, a.x);
                a.y = fmaf(x1[k], w.y, a.y);
                a.z = fmaf(x1[k], w.z, a.z);
                a.w = fmaf(x1[k], w.w, a.w);
            }
            x2[j + 0] = swishf(a.x);
            x2[j + 1] = swishf(a.y);
            x2[j + 2] = swishf(a.z);
            x2[j + 3] = swishf(a.w);
        }

        // ----- layer 3: 16 -> 1 + swish -----
        float a3 = b3s[h];
#pragma unroll
        for (int k = 0; k < HID; k++) a3 = fmaf(x2[k], w3s[h][k], a3);
        float aloc = swishf(a3);

        pre[((size_t)(b * Hh + h) * Nn + n) * Nn + m] = aloc + af * inv_sqrt_c;
    }
}

// ---------------- softmax over m + att@V ----------------
// grid (32 n-tiles, 8 heads, 4 b), 128 threads.
// thread t: row ni = t/8 (16 rows), sub-lane l8 = t%8.
__global__ void softmax_av_kernel(const float* __restrict__ pre,
                                  const float* __restrict__ V,
                                  const int* __restrict__ mask,
                                  float* __restrict__ out) {
    __shared__ float att[16][516];

    int b  = blockIdx.z;
    int h  = blockIdx.y;
    int n0 = blockIdx.x * 16;
    int t  = threadIdx.x;
    int row = t >> 3;
    int l8  = t & 7;

    const float* prow = pre + ((size_t)(b * Hh + h) * Nn + n0) * Nn;
    const int* mk = mask + b * Nn;

    // load + mask + max
    float mx = -3.0e38f;
#pragma unroll 8
    for (int j = 0; j < 64; j++) {
        int m = (j << 3) + l8;
        float v = prow[(size_t)row * Nn + m];
        v = mk[m] ? v : -1e38f;
        att[row][m] = v;
        mx = fmaxf(mx, v);
    }
    mx = fmaxf(mx, __shfl_xor_sync(0xffffffff, mx, 1));
    mx = fmaxf(mx, __shfl_xor_sync(0xffffffff, mx, 2));
    mx = fmaxf(mx, __shfl_xor_sync(0xffffffff, mx, 4));

    // exp + sum
    float s = 0.0f;
#pragma unroll 8
    for (int j = 0; j < 64; j++) {
        int m = (j << 3) + l8;
        float e = __expf(att[row][m] - mx);
        att[row][m] = e;
        s += e;
    }
    s += __shfl_xor_sync(0xffffffff, s, 1);
    s += __shfl_xor_sync(0xffffffff, s, 2);
    s += __shfl_xor_sync(0xffffffff, s, 4);
    float invs = __fdividef(1.0f, s);

    __syncthreads();

    // att @ V : thread computes out[ni][dq*4 .. dq*4+3]
    int ni = row;              // same mapping -> invs is this row's scale
    int dq = l8;
    const float* vp = V + (size_t)b * Nn * Cc + h * Dd + (dq << 2);

    float4 acc = make_float4(0.f, 0.f, 0.f, 0.f);
#pragma unroll 4
    for (int m = 0; m < Nn; m++) {
        float a = att[ni][m];
        float4 v = *(const float4*)(vp + (size_t)m * Cc);
        acc.x = fmaf(a, v.x, acc.x);
        acc.y = fmaf(a, v.y, acc.y);
        acc.z = fmaf(a, v.z, acc.z);
        acc.w = fmaf(a, v.w, acc.w);
    }
    acc.x *= invs; acc.y *= invs; acc.z *= invs; acc.w *= invs;

    *(float4*)&out[(size_t)(b * Nn + n0 + ni) * Cc + h * Dd + (dq << 2)] = acc;
}

// ---------------- launch ----------------
extern "C" void kernel_launch(void* const* d_in, const int* in_sizes, int n_in,
                              void* d_out, int out_size) {
    const float* pg = (const float*)d_in[0];   // pairwise_g
    const float* cs = (const float*)d_in[1];   // coset_functions
    const float* qw = (const float*)d_in[2];
    const float* qb = (const float*)d_in[3];
    const float* kw = (const float*)d_in[4];
    const float* kb = (const float*)d_in[5];
    const float* iw = (const float*)d_in[6];
    const float* ib = (const float*)d_in[7];
    const float* ow = (const float*)d_in[8];
    const float* ob = (const float*)d_in[9];
    const float* w1 = (const float*)d_in[10];
    const float* b1 = (const float*)d_in[11];
    const float* w2 = (const float*)d_in[12];
    const float* b2 = (const float*)d_in[13];
    const float* w3 = (const float*)d_in[14];
    const float* b3 = (const float*)d_in[15];
    const int* mask = (const int*)d_in[16];

    float *Qp, *Kp, *Vp, *Op, *Pp;
    cudaGetSymbolAddress((void**)&Qp, g_Q);
    cudaGetSymbolAddress((void**)&Kp, g_K);
    cudaGetSymbolAddress((void**)&Vp, g_V);
    cudaGetSymbolAddress((void**)&Op, g_O);
    cudaGetSymbolAddress((void**)&Pp, g_pre);

    const int M = Bn * Nn;   // 2048
    dim3 gemm_grid(Cc / 64, M / 64);   // (4, 32)

    gemm_bias_kernel<<<gemm_grid, 256>>>(cs, qw, qb, Qp, M, Cc, Cc);
    gemm_bias_kernel<<<gemm_grid, 256>>>(cs, kw, kb, Kp, M, Cc, Cc);
    gemm_bias_kernel<<<gemm_grid, 256>>>(cs, iw, ib, Vp, M, Cc, Cc);

    logits_kernel<<<dim3(Nn / 16, Nn / 16, Bn), 256>>>(pg, Qp, Kp,
                                                       w1, b1, w2, b2, w3, b3, Pp);

    softmax_av_kernel<<<dim3(Nn / 16, Hh, Bn), 128>>>(Pp, Vp, mask, Op);

    gemm_bias_kernel<<<gemm_grid, 256>>>(Op, ow, ob, (float*)d_out, M, Cc, Cc);
}

// round 4
// speedup vs baseline: 1.2254x; 1.2254x over previous
#include <cuda_runtime.h>
#include <math.h>

typedef unsigned long long ull;

#define Bn 4
#define Nn 512
#define Cc 256
#define Hh 8
#define Dd 32
#define DG 6
#define HID 16

// ---------------- scratch (device globals; no allocation) ----------------
__device__ float g_Q[Bn * Nn * Cc];
__device__ float g_K[Bn * Nn * Cc];
__device__ float g_V[Bn * Nn * Cc];
__device__ float g_O[Bn * Nn * Cc];
__device__ float g_pre[(size_t)Bn * Hh * Nn * Nn];   // [b][h][n][m]

// ---------------- packed f32x2 helpers ----------------
__device__ __forceinline__ ull pack2(float a, float b) {
    ull r; asm("mov.b64 %0, {%1,%2};" : "=l"(r) : "f"(a), "f"(b)); return r;
}
__device__ __forceinline__ void unpack2(ull v, float& a, float& b) {
    asm("mov.b64 {%0,%1}, %2;" : "=f"(a), "=f"(b) : "l"(v));
}
__device__ __forceinline__ ull fma2(ull a, ull b, ull c) {
    ull r; asm("fma.rn.f32x2 %0, %1, %2, %3;" : "=l"(r) : "l"(a), "l"(b), "l"(c)); return r;
}
__device__ __forceinline__ ull mul2(ull a, ull b) {
    ull r; asm("mul.rn.f32x2 %0, %1, %2;" : "=l"(r) : "l"(a), "l"(b)); return r;
}
__device__ __forceinline__ float tanh_ap(float x) {
    float r; asm("tanh.approx.f32 %0, %1;" : "=f"(r) : "f"(x)); return r;
}
__device__ __forceinline__ void lds2u64(ull& a, ull& b, unsigned addr) {
    asm volatile("ld.shared.v2.b64 {%0,%1}, [%2];" : "=l"(a), "=l"(b) : "r"(addr));
}
__device__ __forceinline__ ull lds1u64(unsigned addr) {
    ull a; asm volatile("ld.shared.b64 %0, [%1];" : "=l"(a) : "r"(addr)); return a;
}
__device__ __forceinline__ unsigned s2u(const void* p) {
    unsigned r;
    asm("{.reg .u64 t; cvta.to.shared.u64 t, %1; cvt.u32.u64 %0, t;}" : "=r"(r) : "l"(p));
    return r;
}
// swish(x) = 0.5x*tanh(0.5x) + 0.5x   (packed, 1 MUFU per lane)
__device__ __forceinline__ ull swish2(ull x, ull h2) {
    ull t = mul2(x, h2);
    float a, b; unpack2(t, a, b);
    ull th = pack2(tanh_ap(a), tanh_ap(b));
    return fma2(t, th, t);
}

// ---------------- GEMM body: Y = X(Mx256) @ W(256x256) + bias ----------------
__device__ __forceinline__ void gemm_body(const float* __restrict__ X,
                                          const float* __restrict__ W,
                                          const float* __restrict__ bias,
                                          float* __restrict__ Y) {
    __shared__ float As[16][68];
    __shared__ float Bs[16][68];

    int t  = threadIdx.x;
    int tx = t & 15;
    int ty = t >> 4;
    int m0 = blockIdx.y * 64;
    int n0 = blockIdx.x * 64;

    float acc[4][4];
#pragma unroll
    for (int i = 0; i < 4; i++)
#pragma unroll
        for (int j = 0; j < 4; j++) acc[i][j] = 0.0f;

    for (int k0 = 0; k0 < Cc; k0 += 16) {
        {
            int r = t >> 2;
            int c = (t & 3) << 2;
            float4 v = *(const float4*)&X[(size_t)(m0 + r) * Cc + k0 + c];
            As[c + 0][r] = v.x; As[c + 1][r] = v.y;
            As[c + 2][r] = v.z; As[c + 3][r] = v.w;
        }
        {
            int r = t >> 4;
            int c = (t & 15) << 2;
            *(float4*)&Bs[r][c] = *(const float4*)&W[(size_t)(k0 + r) * Cc + n0 + c];
        }
        __syncthreads();
#pragma unroll
        for (int k = 0; k < 16; k++) {
            float a[4], b[4];
            *(float4*)a = *(const float4*)&As[k][ty << 2];
            *(float4*)b = *(const float4*)&Bs[k][tx << 2];
#pragma unroll
            for (int i = 0; i < 4; i++)
#pragma unroll
                for (int j = 0; j < 4; j++) acc[i][j] = fmaf(a[i], b[j], acc[i][j]);
        }
        __syncthreads();
    }

    float4 bv = *(const float4*)&bias[n0 + (tx << 2)];
#pragma unroll
    for (int i = 0; i < 4; i++) {
        float4 o;
        o.x = acc[i][0] + bv.x; o.y = acc[i][1] + bv.y;
        o.z = acc[i][2] + bv.z; o.w = acc[i][3] + bv.w;
        *(float4*)&Y[(size_t)(m0 + (ty << 2) + i) * Cc + n0 + (tx << 2)] = o;
    }
}

__global__ void gemm_qkv_kernel(const float* __restrict__ X,
                                const float* __restrict__ qw, const float* __restrict__ qb,
                                const float* __restrict__ kw, const float* __restrict__ kb,
                                const float* __restrict__ iw, const float* __restrict__ ib,
                                float* __restrict__ Qp, float* __restrict__ Kp,
                                float* __restrict__ Vp) {
    const float* W; const float* bias; float* Y;
    if (blockIdx.z == 0)      { W = qw; bias = qb; Y = Qp; }
    else if (blockIdx.z == 1) { W = kw; bias = kb; Y = Kp; }
    else                      { W = iw; bias = ib; Y = Vp; }
    gemm_body(X, W, bias, Y);
}

__global__ void gemm_out_kernel(const float* __restrict__ X,
                                const float* __restrict__ ow, const float* __restrict__ ob,
                                float* __restrict__ Yout) {
    gemm_body(X, ow, ob, Yout);
}

// ---------------- logits: pre[b][h][n][m] = A_loc + A_feat ----------------
// CTA: 16 n x 32 m, 256 threads; thread = (ni, mg) handles m = m0+2*mg, +1 packed f32x2.
#define LOGITS_SMEM_BYTES (18832 * 4)

__global__ __launch_bounds__(256, 2)
void logits_kernel(const float* __restrict__ g,
                   const float* __restrict__ Q,
                   const float* __restrict__ K,
                   const float* __restrict__ w1, const float* __restrict__ b1,
                   const float* __restrict__ w2, const float* __restrict__ b2,
                   const float* __restrict__ w3, const float* __restrict__ b3,
                   float* __restrict__ pre) {
    extern __shared__ float sm[];
    float*  Qs  = sm;
    float*  Kt  = sm + 4224;
    float2* w1d = (float2*)(sm + 12416);
    float2* w2d = (float2*)(sm + 13952);
    float2* w3d = (float2*)(sm + 18048);
    float2* b1d = (float2*)(sm + 18304);
    float2* b2d = (float2*)(sm + 18560);
    float2* b3d = (float2*)(sm + 18816);

    int b  = blockIdx.z;
    int n0 = blockIdx.y * 16;
    int m0 = blockIdx.x * 32;
    int t  = threadIdx.x;

    // duplicated weights
    for (int i = t; i < Hh * DG * HID; i += 256) { float v = w1[i]; w1d[i] = make_float2(v, v); }
    for (int i = t; i < Hh * HID * HID; i += 256){ float v = w2[i]; w2d[i] = make_float2(v, v); }
    if (t < Hh * HID) {
        float v = w3[t]; w3d[t] = make_float2(v, v);
        float u = b1[t]; b1d[t] = make_float2(u, u);
        float z = b2[t]; b2d[t] = make_float2(z, z);
    }
    if (t < Hh) { float v = b3[t]; b3d[t] = make_float2(v, v); }

    // Q tile [16 n][256 c]
    {
        int r = t >> 4, c = (t & 15) << 4;
        const float* src = Q + (size_t)(b * Nn + n0 + r) * Cc + c;
#pragma unroll
        for (int v = 0; v < 4; v++)
            *(float4*)&Qs[r * 264 + c + v * 4] = *(const float4*)(src + v * 4);
    }
    // K tile transposed: Kt[c][m], via 4x4 register-block transpose (2 blocks/thread)
#pragma unroll
    for (int bi = 0; bi < 2; bi++) {
        int blk = t + bi * 256;          // 0..511
        int bm = (blk & 7) << 2;         // m within tile
        int bc = (blk >> 3) << 2;        // c
        const float* kp = K + (size_t)(b * Nn + m0 + bm) * Cc + bc;
        float4 r0 = *(const float4*)kp;
        float4 r1 = *(const float4*)(kp + Cc);
        float4 r2 = *(const float4*)(kp + 2 * Cc);
        float4 r3 = *(const float4*)(kp + 3 * Cc);
        *(float4*)&Kt[(bc + 0) * 32 + bm] = make_float4(r0.x, r1.x, r2.x, r3.x);
        *(float4*)&Kt[(bc + 1) * 32 + bm] = make_float4(r0.y, r1.y, r2.y, r3.y);
        *(float4*)&Kt[(bc + 2) * 32 + bm] = make_float4(r0.z, r1.z, r2.z, r3.z);
        *(float4*)&Kt[(bc + 3) * 32 + bm] = make_float4(r0.w, r1.w, r2.w, r3.w);
    }
    __syncthreads();

    int ni = t >> 4, mg = t & 15;
    int n = n0 + ni, m = m0 + mg * 2;

    // pairwise_g packed: gv2[k] = {g[n][m][k], g[n][m+1][k]}
    ull gv2[6];
    {
        const float* gp = g + ((size_t)(b * Nn + n) * Nn + m) * DG;
        float4 f0 = *(const float4*)gp;
        float4 f1 = *(const float4*)(gp + 4);
        float4 f2 = *(const float4*)(gp + 8);
        gv2[0] = pack2(f0.x, f1.z); gv2[1] = pack2(f0.y, f1.w);
        gv2[2] = pack2(f0.z, f2.x); gv2[3] = pack2(f0.w, f2.y);
        gv2[4] = pack2(f1.x, f2.z); gv2[5] = pack2(f1.y, f2.w);
    }

    const ull h2 = pack2(0.5f, 0.5f);
    unsigned w1a = s2u(w1d), w2a = s2u(w2d), w3a = s2u(w3d);
    unsigned b1a = s2u(b1d), b2a = s2u(b2d), b3a = s2u(b3d);
    unsigned kta = s2u(Kt) + mg * 8;   // byte addr of Kt[0][2*mg]

#pragma unroll 1
    for (int h = 0; h < Hh; h++) {
        // ----- layer 1: 6 -> 16, packed -----
        ull x[16];
        {
            unsigned ba = b1a + h * 128;
#pragma unroll
            for (int j = 0; j < 16; j += 2) lds2u64(x[j], x[j + 1], ba + j * 8);
        }
#pragma unroll
        for (int k = 0; k < DG; k++) {
            unsigned wa = w1a + (h * DG + k) * 128;
#pragma unroll
            for (int j = 0; j < 16; j += 2) {
                ull wlo, whi; lds2u64(wlo, whi, wa + j * 8);
                x[j]     = fma2(gv2[k], wlo, x[j]);
                x[j + 1] = fma2(gv2[k], whi, x[j + 1]);
            }
        }
#pragma unroll
        for (int j = 0; j < 16; j++) x[j] = swish2(x[j], h2);

        // ----- layer 2: 16 -> 16, packed -----
        ull y[16];
        {
            unsigned ba = b2a + h * 128;
#pragma unroll
            for (int j = 0; j < 16; j += 2) lds2u64(y[j], y[j + 1], ba + j * 8);
        }
#pragma unroll
        for (int k = 0; k < HID; k++) {
            unsigned wa = w2a + (h * HID + k) * 128;
#pragma unroll
            for (int j = 0; j < 16; j += 2) {
                ull wlo, whi; lds2u64(wlo, whi, wa + j * 8);
                y[j]     = fma2(x[k], wlo, y[j]);
                y[j + 1] = fma2(x[k], whi, y[j + 1]);
            }
        }
#pragma unroll
        for (int j = 0; j < 16; j++) y[j] = swish2(y[j], h2);

        // ----- layer 3: 16 -> 1, packed -----
        ull a3 = lds1u64(b3a + h * 8);
#pragma unroll
        for (int k = 0; k < HID; k += 2) {
            ull wlo, whi; lds2u64(wlo, whi, w3a + h * 128 + k * 8);
            a3 = fma2(y[k], wlo, a3);
            a3 = fma2(y[k + 1], whi, a3);
        }
        ull aloc = swish2(a3, h2);

        // ----- A_feat: packed dot over head's 32 channels from Kt -----
        ull af2 = pack2(0.0f, 0.0f);
        unsigned kh = kta + (h * 32) * 128;   // channel row = 32 floats = 128 B
#pragma unroll
        for (int cc = 0; cc < 32; cc += 4) {
            float4 q4 = *(const float4*)&Qs[ni * 264 + h * 32 + cc];
            ull k0 = lds1u64(kh + (cc + 0) * 128);
            ull k1 = lds1u64(kh + (cc + 1) * 128);
            ull k2 = lds1u64(kh + (cc + 2) * 128);
            ull k3 = lds1u64(kh + (cc + 3) * 128);
            af2 = fma2(k0, pack2(q4.x, q4.x), af2);
            af2 = fma2(k1, pack2(q4.y, q4.y), af2);
            af2 = fma2(k2, pack2(q4.z, q4.z), af2);
            af2 = fma2(k3, pack2(q4.w, q4.w), af2);
        }
        float af0, af1; unpack2(af2, af0, af1);
        float l0, l1;  unpack2(aloc, l0, l1);
        float2 o = make_float2(l0 + af0 * 0.0625f, l1 + af1 * 0.0625f);
        *(float2*)&pre[((size_t)(b * Hh + h) * Nn + n) * Nn + m] = o;
    }
}

// ---------------- softmax over m + att@V ----------------
__global__ void softmax_av_kernel(const float* __restrict__ pre,
                                  const float* __restrict__ V,
                                  const int* __restrict__ mask,
                                  float* __restrict__ out) {
    __shared__ float att[16][516];

    int b  = blockIdx.z;
    int h  = blockIdx.y;
    int n0 = blockIdx.x * 16;
    int t  = threadIdx.x;
    int row = t >> 3;
    int l8  = t & 7;

    const float4* prow = (const float4*)(pre + ((size_t)(b * Hh + h) * Nn + n0 + row) * Nn);
    const int4*   mk4  = (const int4*)(mask + b * Nn);

    float4 buf[16];
    float mx = -3.0e38f;
#pragma unroll
    for (int j = 0; j < 16; j++) {
        int i4 = j * 8 + l8;
        float4 v = prow[i4];
        int4  mm = mk4[i4];
        v.x = mm.x ? v.x : -1e38f;
        v.y = mm.y ? v.y : -1e38f;
        v.z = mm.z ? v.z : -1e38f;
        v.w = mm.w ? v.w : -1e38f;
        buf[j] = v;
        mx = fmaxf(mx, fmaxf(fmaxf(v.x, v.y), fmaxf(v.z, v.w)));
    }
    mx = fmaxf(mx, __shfl_xor_sync(0xffffffff, mx, 1));
    mx = fmaxf(mx, __shfl_xor_sync(0xffffffff, mx, 2));
    mx = fmaxf(mx, __shfl_xor_sync(0xffffffff, mx, 4));

    float s = 0.0f;
#pragma unroll
    for (int j = 0; j < 16; j++) {
        int i4 = j * 8 + l8;
        float4 v = buf[j];
        float4 e;
        e.x = __expf(v.x - mx); e.y = __expf(v.y - mx);
        e.z = __expf(v.z - mx); e.w = __expf(v.w - mx);
        s += e.x + e.y + e.z + e.w;
        *(float4*)&att[row][i4 * 4] = e;
    }
    s += __shfl_xor_sync(0xffffffff, s, 1);
    s += __shfl_xor_sync(0xffffffff, s, 2);
    s += __shfl_xor_sync(0xffffffff, s, 4);
    float invs = __fdividef(1.0f, s);

    __syncthreads();

    // att @ V
    int ni = row;
    int dq = l8;
    const float* vp = V + (size_t)b * Nn * Cc + h * Dd + (dq << 2);

    float4 acc = make_float4(0.f, 0.f, 0.f, 0.f);
#pragma unroll 4
    for (int m = 0; m < Nn; m++) {
        float a = att[ni][m];
        float4 v = *(const float4*)(vp + (size_t)m * Cc);
        acc.x = fmaf(a, v.x, acc.x);
        acc.y = fmaf(a, v.y, acc.y);
        acc.z = fmaf(a, v.z, acc.z);
        acc.w = fmaf(a, v.w, acc.w);
    }
    acc.x *= invs; acc.y *= invs; acc.z *= invs; acc.w *= invs;

    *(float4*)&out[(size_t)(b * Nn + n0 + ni) * Cc + h * Dd + (dq << 2)] = acc;
}

// ---------------- launch ----------------
extern "C" void kernel_launch(void* const* d_in, const int* in_sizes, int n_in,
                              void* d_out, int out_size) {
    const float* pg = (const float*)d_in[0];
    const float* cs = (const float*)d_in[1];
    const float* qw = (const float*)d_in[2];
    const float* qb = (const float*)d_in[3];
    const float* kw = (const float*)d_in[4];
    const float* kb = (const float*)d_in[5];
    const float* iw = (const float*)d_in[6];
    const float* ib = (const float*)d_in[7];
    const float* ow = (const float*)d_in[8];
    const float* ob = (const float*)d_in[9];
    const float* w1 = (const float*)d_in[10];
    const float* b1 = (const float*)d_in[11];
    const float* w2 = (const float*)d_in[12];
    const float* b2 = (const float*)d_in[13];
    const float* w3 = (const float*)d_in[14];
    const float* b3 = (const float*)d_in[15];
    const int*  mask = (const int*)d_in[16];

    float *Qp, *Kp, *Vp, *Op, *Pp;
    cudaGetSymbolAddress((void**)&Qp, g_Q);
    cudaGetSymbolAddress((void**)&Kp, g_K);
    cudaGetSymbolAddress((void**)&Vp, g_V);
    cudaGetSymbolAddress((void**)&Op, g_O);
    cudaGetSymbolAddress((void**)&Pp, g_pre);

    cudaFuncSetAttribute(logits_kernel,
                         cudaFuncAttributeMaxDynamicSharedMemorySize,
                         LOGITS_SMEM_BYTES);

    const int M = Bn * Nn;   // 2048

    gemm_qkv_kernel<<<dim3(Cc / 64, M / 64, 3), 256>>>(cs, qw, qb, kw, kb, iw, ib,
                                                       Qp, Kp, Vp);

    logits_kernel<<<dim3(Nn / 32, Nn / 16, Bn), 256, LOGITS_SMEM_BYTES>>>(
        pg, Qp, Kp, w1, b1, w2, b2, w3, b3, Pp);

    softmax_av_kernel<<<dim3(Nn / 16, Hh, Bn), 128>>>(Pp, Vp, mask, Op);

    gemm_out_kernel<<<dim3(Cc / 64, M / 64), 256>>>(Op, ow, ob, (float*)d_out);
}

// round 5
// speedup vs baseline: 1.4573x; 1.1892x over previous
#include <cuda_runtime.h>
#include <math.h>

typedef unsigned long long ull;

#define Bn 4
#define Nn 512
#define Cc 256
#define Hh 8
#define Dd 32
#define DG 6
#define HID 16

// ---------------- scratch (device globals; no allocation) ----------------
__device__ float g_Q[Bn * Nn * Cc];
__device__ float g_K[Bn * Nn * Cc];
__device__ float g_V[Bn * Nn * Cc];
__device__ float g_O[Bn * Nn * Cc];
__device__ float g_pre[(size_t)Bn * Hh * Nn * Nn];   // [b][h][n][m]

// ---------------- packed f32x2 helpers ----------------
__device__ __forceinline__ ull pack2(float a, float b) {
    ull r; asm("mov.b64 %0, {%1,%2};" : "=l"(r) : "f"(a), "f"(b)); return r;
}
__device__ __forceinline__ void unpack2(ull v, float& a, float& b) {
    asm("mov.b64 {%0,%1}, %2;" : "=f"(a), "=f"(b) : "l"(v));
}
__device__ __forceinline__ ull fma2(ull a, ull b, ull c) {
    ull r; asm("fma.rn.f32x2 %0, %1, %2, %3;" : "=l"(r) : "l"(a), "l"(b), "l"(c)); return r;
}
__device__ __forceinline__ ull mul2(ull a, ull b) {
    ull r; asm("mul.rn.f32x2 %0, %1, %2;" : "=l"(r) : "l"(a), "l"(b)); return r;
}
__device__ __forceinline__ float tanh_ap(float x) {
    float r; asm("tanh.approx.f32 %0, %1;" : "=f"(r) : "f"(x)); return r;
}
__device__ __forceinline__ void lds2u64(ull& a, ull& b, unsigned addr) {
    asm volatile("ld.shared.v2.b64 {%0,%1}, [%2];" : "=l"(a), "=l"(b) : "r"(addr));
}
__device__ __forceinline__ ull lds1u64(unsigned addr) {
    ull a; asm volatile("ld.shared.b64 %0, [%1];" : "=l"(a) : "r"(addr)); return a;
}
__device__ __forceinline__ unsigned s2u(const void* p) {
    unsigned r;
    asm("{.reg .u64 t; cvta.to.shared.u64 t, %1; cvt.u32.u64 %0, t;}" : "=r"(r) : "l"(p));
    return r;
}
// swish(x) = 0.5x*tanh(0.5x) + 0.5x   (packed, 1 MUFU per lane)
__device__ __forceinline__ ull swish2(ull x, ull h2) {
    ull t = mul2(x, h2);
    float a, b; unpack2(t, a, b);
    ull th = pack2(tanh_ap(a), tanh_ap(b));
    return fma2(t, th, t);
}

// ---------------- GEMM body: Y = X(Mx256) @ W(256x256) + bias ----------------
__device__ __forceinline__ void gemm_body(const float* __restrict__ X,
                                          const float* __restrict__ W,
                                          const float* __restrict__ bias,
                                          float* __restrict__ Y) {
    __shared__ float As[16][68];
    __shared__ float Bs[16][68];

    int t  = threadIdx.x;
    int tx = t & 15;
    int ty = t >> 4;
    int m0 = blockIdx.y * 64;
    int n0 = blockIdx.x * 64;

    float acc[4][4];
#pragma unroll
    for (int i = 0; i < 4; i++)
#pragma unroll
        for (int j = 0; j < 4; j++) acc[i][j] = 0.0f;

    for (int k0 = 0; k0 < Cc; k0 += 16) {
        {
            int r = t >> 2;
            int c = (t & 3) << 2;
            float4 v = *(const float4*)&X[(size_t)(m0 + r) * Cc + k0 + c];
            As[c + 0][r] = v.x; As[c + 1][r] = v.y;
            As[c + 2][r] = v.z; As[c + 3][r] = v.w;
        }
        {
            int r = t >> 4;
            int c = (t & 15) << 2;
            *(float4*)&Bs[r][c] = *(const float4*)&W[(size_t)(k0 + r) * Cc + n0 + c];
        }
        __syncthreads();
#pragma unroll
        for (int k = 0; k < 16; k++) {
            float a[4], b[4];
            *(float4*)a = *(const float4*)&As[k][ty << 2];
            *(float4*)b = *(const float4*)&Bs[k][tx << 2];
#pragma unroll
            for (int i = 0; i < 4; i++)
#pragma unroll
                for (int j = 0; j < 4; j++) acc[i][j] = fmaf(a[i], b[j], acc[i][j]);
        }
        __syncthreads();
    }

    float4 bv = *(const float4*)&bias[n0 + (tx << 2)];
#pragma unroll
    for (int i = 0; i < 4; i++) {
        float4 o;
        o.x = acc[i][0] + bv.x; o.y = acc[i][1] + bv.y;
        o.z = acc[i][2] + bv.z; o.w = acc[i][3] + bv.w;
        *(float4*)&Y[(size_t)(m0 + (ty << 2) + i) * Cc + n0 + (tx << 2)] = o;
    }
}

__global__ void gemm_qkv_kernel(const float* __restrict__ X,
                                const float* __restrict__ qw, const float* __restrict__ qb,
                                const float* __restrict__ kw, const float* __restrict__ kb,
                                const float* __restrict__ iw, const float* __restrict__ ib,
                                float* __restrict__ Qp, float* __restrict__ Kp,
                                float* __restrict__ Vp) {
    const float* W; const float* bias; float* Y;
    if (blockIdx.z == 0)      { W = qw; bias = qb; Y = Qp; }
    else if (blockIdx.z == 1) { W = kw; bias = kb; Y = Kp; }
    else                      { W = iw; bias = ib; Y = Vp; }
    gemm_body(X, W, bias, Y);
}

__global__ void gemm_out_kernel(const float* __restrict__ X,
                                const float* __restrict__ ow, const float* __restrict__ ob,
                                float* __restrict__ Yout) {
    gemm_body(X, ow, ob, Yout);
}

// ---------------- logits: pre[b][h][n][m] = A_loc + A_feat ----------------
// CTA: 16 n x 32 m tile, 128 threads.
// Thread (ni = t>>4 in 0..7, mg = t&15): rows 2ni, 2ni+1; m-pair m0+2mg (f32x2).
// => 4 (n,m) pairs per thread; every weight LDS.128 feeds 4 FFMA2.
// smem (floats): Qs[16][260]@0 (4160) | Kt[256][32]@4160 (8192) |
//   w1d@12352 (1536) | w2d@13888 (4096) | w3d@17984 (256) |
//   b1d@18240 (256) | b2d@18496 (256) | b3d@18752 (16)  -> 18768 fl = 75072 B
#define LOGITS_SMEM_BYTES (18768 * 4)

__global__ __launch_bounds__(128, 3)
void logits_kernel(const float* __restrict__ g,
                   const float* __restrict__ Q,
                   const float* __restrict__ K,
                   const float* __restrict__ w1, const float* __restrict__ b1,
                   const float* __restrict__ w2, const float* __restrict__ b2,
                   const float* __restrict__ w3, const float* __restrict__ b3,
                   float* __restrict__ pre) {
    extern __shared__ float sm[];
    float*  Qs  = sm;
    float*  Kt  = sm + 4160;
    float2* w1d = (float2*)(sm + 12352);
    float2* w2d = (float2*)(sm + 13888);
    float2* w3d = (float2*)(sm + 17984);
    float2* b1d = (float2*)(sm + 18240);
    float2* b2d = (float2*)(sm + 18496);
    float2* b3d = (float2*)(sm + 18752);

    int b  = blockIdx.z;
    int n0 = blockIdx.y * 16;
    int m0 = blockIdx.x * 32;
    int t  = threadIdx.x;

    // duplicated weights (cooperative, 128 threads)
#pragma unroll
    for (int i = t; i < Hh * DG * HID; i += 128) { float v = w1[i]; w1d[i] = make_float2(v, v); }
#pragma unroll
    for (int i = t; i < Hh * HID * HID; i += 128){ float v = w2[i]; w2d[i] = make_float2(v, v); }
    {
        float v = w3[t]; w3d[t] = make_float2(v, v);
        float u = b1[t]; b1d[t] = make_float2(u, u);
        float z = b2[t]; b2d[t] = make_float2(z, z);
    }
    if (t < Hh) { float v = b3[t]; b3d[t] = make_float2(v, v); }

    // Q tile [16 n][256 c]
    {
        int r = t >> 3, c = (t & 7) << 5;   // 32 floats per thread
        const float* src = Q + (size_t)(b * Nn + n0 + r) * Cc + c;
#pragma unroll
        for (int v = 0; v < 8; v++)
            *(float4*)&Qs[r * 260 + c + v * 4] = *(const float4*)(src + v * 4);
    }
    // K tile transposed: Kt[c][m] (4x4 register-block transpose, 4 blocks/thread)
#pragma unroll
    for (int bi = 0; bi < 4; bi++) {
        int blk = t + bi * 128;          // 0..511
        int bm = (blk & 7) << 2;
        int bc = (blk >> 3) << 2;
        const float* kp = K + (size_t)(b * Nn + m0 + bm) * Cc + bc;
        float4 r0 = *(const float4*)kp;
        float4 r1 = *(const float4*)(kp + Cc);
        float4 r2 = *(const float4*)(kp + 2 * Cc);
        float4 r3 = *(const float4*)(kp + 3 * Cc);
        *(float4*)&Kt[(bc + 0) * 32 + bm] = make_float4(r0.x, r1.x, r2.x, r3.x);
        *(float4*)&Kt[(bc + 1) * 32 + bm] = make_float4(r0.y, r1.y, r2.y, r3.y);
        *(float4*)&Kt[(bc + 2) * 32 + bm] = make_float4(r0.z, r1.z, r2.z, r3.z);
        *(float4*)&Kt[(bc + 3) * 32 + bm] = make_float4(r0.w, r1.w, r2.w, r3.w);
    }
    __syncthreads();

    int ni = t >> 4, mg = t & 15;
    int nr0 = n0 + 2 * ni;               // global row 0 (row 1 = +1)
    int m   = m0 + 2 * mg;

    // pairwise_g packed for both rows: g?[k] = {g[n][m][k], g[n][m+1][k]}
    ull ga[6], gb[6];
    {
        const float* gp0 = g + ((size_t)(b * Nn + nr0) * Nn + m) * DG;
        const float* gp1 = gp0 + (size_t)Nn * DG;
        float4 f0 = *(const float4*)gp0;
        float4 f1 = *(const float4*)(gp0 + 4);
        float4 f2 = *(const float4*)(gp0 + 8);
        ga[0] = pack2(f0.x, f1.z); ga[1] = pack2(f0.y, f1.w);
        ga[2] = pack2(f0.z, f2.x); ga[3] = pack2(f0.w, f2.y);
        ga[4] = pack2(f1.x, f2.z); ga[5] = pack2(f1.y, f2.w);
        float4 e0 = *(const float4*)gp1;
        float4 e1 = *(const float4*)(gp1 + 4);
        float4 e2 = *(const float4*)(gp1 + 8);
        gb[0] = pack2(e0.x, e1.z); gb[1] = pack2(e0.y, e1.w);
        gb[2] = pack2(e0.z, e2.x); gb[3] = pack2(e0.w, e2.y);
        gb[4] = pack2(e1.x, e2.z); gb[5] = pack2(e1.y, e2.w);
    }

    const ull h2 = pack2(0.5f, 0.5f);
    unsigned w1a = s2u(w1d), w2a = s2u(w2d), w3a = s2u(w3d);
    unsigned b1a = s2u(b1d), b2a = s2u(b2d), b3a = s2u(b3d);
    unsigned kta = s2u(Kt) + mg * 8;

#pragma unroll 1
    for (int h = 0; h < Hh; h++) {
        // ----- layer 1: 6 -> 16, both rows -----
        ull x0[16], x1[16];
        {
            unsigned ba = b1a + h * 128;
#pragma unroll
            for (int j = 0; j < 16; j += 2) {
                lds2u64(x0[j], x0[j + 1], ba + j * 8);
                x1[j] = x0[j]; x1[j + 1] = x0[j + 1];
            }
        }
#pragma unroll
        for (int k = 0; k < DG; k++) {
            unsigned wa = w1a + (h * DG + k) * 128;
#pragma unroll
            for (int j = 0; j < 16; j += 2) {
                ull wlo, whi; lds2u64(wlo, whi, wa + j * 8);
                x0[j]     = fma2(ga[k], wlo, x0[j]);
                x0[j + 1] = fma2(ga[k], whi, x0[j + 1]);
                x1[j]     = fma2(gb[k], wlo, x1[j]);
                x1[j + 1] = fma2(gb[k], whi, x1[j + 1]);
            }
        }
#pragma unroll
        for (int j = 0; j < 16; j++) { x0[j] = swish2(x0[j], h2); x1[j] = swish2(x1[j], h2); }

        // ----- layer 2 (in two j-halves) + layer 3 folded in -----
        ull a30 = lds1u64(b3a + h * 8);
        ull a31 = a30;
#pragma unroll
        for (int jh = 0; jh < 2; jh++) {
            ull y0[8], y1[8];
            unsigned ba = b2a + h * 128 + jh * 64;
#pragma unroll
            for (int j = 0; j < 8; j += 2) {
                lds2u64(y0[j], y0[j + 1], ba + j * 8);
                y1[j] = y0[j]; y1[j + 1] = y0[j + 1];
            }
#pragma unroll
            for (int k = 0; k < HID; k++) {
                unsigned wa = w2a + (h * HID + k) * 128 + jh * 64;
#pragma unroll
                for (int j = 0; j < 8; j += 2) {
                    ull wlo, whi; lds2u64(wlo, whi, wa + j * 8);
                    y0[j]     = fma2(x0[k], wlo, y0[j]);
                    y0[j + 1] = fma2(x0[k], whi, y0[j + 1]);
                    y1[j]     = fma2(x1[k], wlo, y1[j]);
                    y1[j + 1] = fma2(x1[k], whi, y1[j + 1]);
                }
            }
#pragma unroll
            for (int j = 0; j < 8; j++) { y0[j] = swish2(y0[j], h2); y1[j] = swish2(y1[j], h2); }
#pragma unroll
            for (int j = 0; j < 8; j += 2) {
                ull wlo, whi; lds2u64(wlo, whi, w3a + h * 128 + jh * 64 + j * 8);
                a30 = fma2(y0[j], wlo, a30); a30 = fma2(y0[j + 1], whi, a30);
                a31 = fma2(y1[j], wlo, a31); a31 = fma2(y1[j + 1], whi, a31);
            }
        }
        ull aloc0 = swish2(a30, h2);
        ull aloc1 = swish2(a31, h2);

        // ----- A_feat for both rows (K channels shared) -----
        ull af0 = pack2(0.0f, 0.0f), af1 = af0;
        unsigned kh = kta + (h * 32) * 128;
#pragma unroll
        for (int cc = 0; cc < 32; cc += 4) {
            float4 q0 = *(const float4*)&Qs[(2 * ni) * 260 + h * 32 + cc];
            float4 q1 = *(const float4*)&Qs[(2 * ni + 1) * 260 + h * 32 + cc];
            ull k0 = lds1u64(kh + (cc + 0) * 128);
            ull k1 = lds1u64(kh + (cc + 1) * 128);
            ull k2 = lds1u64(kh + (cc + 2) * 128);
            ull k3 = lds1u64(kh + (cc + 3) * 128);
            af0 = fma2(k0, pack2(q0.x, q0.x), af0);
            af0 = fma2(k1, pack2(q0.y, q0.y), af0);
            af0 = fma2(k2, pack2(q0.z, q0.z), af0);
            af0 = fma2(k3, pack2(q0.w, q0.w), af0);
            af1 = fma2(k0, pack2(q1.x, q1.x), af1);
            af1 = fma2(k1, pack2(q1.y, q1.y), af1);
            af1 = fma2(k2, pack2(q1.z, q1.z), af1);
            af1 = fma2(k3, pack2(q1.w, q1.w), af1);
        }

        float a0, a1, l0, l1;
        float* pr = pre + ((size_t)(b * Hh + h) * Nn + nr0) * Nn + m;
        unpack2(af0, a0, a1); unpack2(aloc0, l0, l1);
        *(float2*)pr = make_float2(l0 + a0 * 0.0625f, l1 + a1 * 0.0625f);
        unpack2(af1, a0, a1); unpack2(aloc1, l0, l1);
        *(float2*)(pr + Nn) = make_float2(l0 + a0 * 0.0625f, l1 + a1 * 0.0625f);
    }
}

// ---------------- softmax over m + att@V ----------------
__global__ void softmax_av_kernel(const float* __restrict__ pre,
                                  const float* __restrict__ V,
                                  const int* __restrict__ mask,
                                  float* __restrict__ out) {
    __shared__ float att[16][516];

    int b  = blockIdx.z;
    int h  = blockIdx.y;
    int n0 = blockIdx.x * 16;
    int t  = threadIdx.x;
    int row = t >> 3;
    int l8  = t & 7;

    const float4* prow = (const float4*)(pre + ((size_t)(b * Hh + h) * Nn + n0 + row) * Nn);
    const int4*   mk4  = (const int4*)(mask + b * Nn);

    float4 buf[16];
    float mx = -3.0e38f;
#pragma unroll
    for (int j = 0; j < 16; j++) {
        int i4 = j * 8 + l8;
        float4 v = prow[i4];
        int4  mm = mk4[i4];
        v.x = mm.x ? v.x : -1e38f;
        v.y = mm.y ? v.y : -1e38f;
        v.z = mm.z ? v.z : -1e38f;
        v.w = mm.w ? v.w : -1e38f;
        buf[j] = v;
        mx = fmaxf(mx, fmaxf(fmaxf(v.x, v.y), fmaxf(v.z, v.w)));
    }
    mx = fmaxf(mx, __shfl_xor_sync(0xffffffff, mx, 1));
    mx = fmaxf(mx, __shfl_xor_sync(0xffffffff, mx, 2));
    mx = fmaxf(mx, __shfl_xor_sync(0xffffffff, mx, 4));

    float s = 0.0f;
#pragma unroll
    for (int j = 0; j < 16; j++) {
        int i4 = j * 8 + l8;
        float4 v = buf[j];
        float4 e;
        e.x = __expf(v.x - mx); e.y = __expf(v.y - mx);
        e.z = __expf(v.z - mx); e.w = __expf(v.w - mx);
        s += e.x + e.y + e.z + e.w;
        *(float4*)&att[row][i4 * 4] = e;
    }
    s += __shfl_xor_sync(0xffffffff, s, 1);
    s += __shfl_xor_sync(0xffffffff, s, 2);
    s += __shfl_xor_sync(0xffffffff, s, 4);
    float invs = __fdividef(1.0f, s);

    __syncthreads();

    // att @ V
    int ni = row;
    int dq = l8;
    const float* vp = V + (size_t)b * Nn * Cc + h * Dd + (dq << 2);

    float4 acc = make_float4(0.f, 0.f, 0.f, 0.f);
#pragma unroll 4
    for (int m = 0; m < Nn; m++) {
        float a = att[ni][m];
        float4 v = *(const float4*)(vp + (size_t)m * Cc);
        acc.x = fmaf(a, v.x, acc.x);
        acc.y = fmaf(a, v.y, acc.y);
        acc.z = fmaf(a, v.z, acc.z);
        acc.w = fmaf(a, v.w, acc.w);
    }
    acc.x *= invs; acc.y *= invs; acc.z *= invs; acc.w *= invs;

    *(float4*)&out[(size_t)(b * Nn + n0 + ni) * Cc + h * Dd + (dq << 2)] = acc;
}

// ---------------- launch ----------------
extern "C" void kernel_launch(void* const* d_in, const int* in_sizes, int n_in,
                              void* d_out, int out_size) {
    const float* pg = (const float*)d_in[0];
    const float* cs = (const float*)d_in[1];
    const float* qw = (const float*)d_in[2];
    const float* qb = (const float*)d_in[3];
    const float* kw = (const float*)d_in[4];
    const float* kb = (const float*)d_in[5];
    const float* iw = (const float*)d_in[6];
    const float* ib = (const float*)d_in[7];
    const float* ow = (const float*)d_in[8];
    const float* ob = (const float*)d_in[9];
    const float* w1 = (const float*)d_in[10];
    const float* b1 = (const float*)d_in[11];
    const float* w2 = (const float*)d_in[12];
    const float* b2 = (const float*)d_in[13];
    const float* w3 = (const float*)d_in[14];
    const float* b3 = (const float*)d_in[15];
    const int*  mask = (const int*)d_in[16];

    float *Qp, *Kp, *Vp, *Op, *Pp;
    cudaGetSymbolAddress((void**)&Qp, g_Q);
    cudaGetSymbolAddress((void**)&Kp, g_K);
    cudaGetSymbolAddress((void**)&Vp, g_V);
    cudaGetSymbolAddress((void**)&Op, g_O);
    cudaGetSymbolAddress((void**)&Pp, g_pre);

    cudaFuncSetAttribute(logits_kernel,
                         cudaFuncAttributeMaxDynamicSharedMemorySize,
                         LOGITS_SMEM_BYTES);

    const int M = Bn * Nn;   // 2048

    gemm_qkv_kernel<<<dim3(Cc / 64, M / 64, 3), 256>>>(cs, qw, qb, kw, kb, iw, ib,
                                                       Qp, Kp, Vp);

    logits_kernel<<<dim3(Nn / 32, Nn / 16, Bn), 128, LOGITS_SMEM_BYTES>>>(
        pg, Qp, Kp, w1, b1, w2, b2, w3, b3, Pp);

    softmax_av_kernel<<<dim3(Nn / 16, Hh, Bn), 128>>>(Pp, Vp, mask, Op);

    gemm_out_kernel<<<dim3(Cc / 64, M / 64), 256>>>(Op, ow, ob, (float*)d_out);
}

// round 6
// speedup vs baseline: 1.5813x; 1.0851x over previous
#include <cuda_runtime.h>
#include <math.h>

typedef unsigned long long ull;

#define Bn 4
#define Nn 512
#define Cc 256
#define Hh 8
#define Dd 32
#define DG 6
#define HID 16

// ---------------- scratch (device globals; no allocation) ----------------
__device__ float g_Q[Bn * Nn * Cc];
__device__ float g_K[Bn * Nn * Cc];
__device__ float g_V[Bn * Nn * Cc];
__device__ float g_O[Bn * Nn * Cc];
__device__ float g_pre[(size_t)Bn * Hh * Nn * Nn];   // [b][h][n][m]

// ---------------- packed f32x2 helpers ----------------
__device__ __forceinline__ ull pack2(float a, float b) {
    ull r; asm("mov.b64 %0, {%1,%2};" : "=l"(r) : "f"(a), "f"(b)); return r;
}
__device__ __forceinline__ void unpack2(ull v, float& a, float& b) {
    asm("mov.b64 {%0,%1}, %2;" : "=f"(a), "=f"(b) : "l"(v));
}
__device__ __forceinline__ ull fma2(ull a, ull b, ull c) {
    ull r; asm("fma.rn.f32x2 %0, %1, %2, %3;" : "=l"(r) : "l"(a), "l"(b), "l"(c)); return r;
}
__device__ __forceinline__ ull mul2(ull a, ull b) {
    ull r; asm("mul.rn.f32x2 %0, %1, %2;" : "=l"(r) : "l"(a), "l"(b)); return r;
}
__device__ __forceinline__ float tanh_ap(float x) {
    float r; asm("tanh.approx.f32 %0, %1;" : "=f"(r) : "f"(x)); return r;
}
__device__ __forceinline__ void lds2u64(ull& a, ull& b, unsigned addr) {
    asm volatile("ld.shared.v2.b64 {%0,%1}, [%2];" : "=l"(a), "=l"(b) : "r"(addr));
}
__device__ __forceinline__ ull lds1u64(unsigned addr) {
    ull a; asm volatile("ld.shared.b64 %0, [%1];" : "=l"(a) : "r"(addr)); return a;
}
__device__ __forceinline__ unsigned s2u(const void* p) {
    unsigned r;
    asm("{.reg .u64 t; cvta.to.shared.u64 t, %1; cvt.u32.u64 %0, t;}" : "=r"(r) : "l"(p));
    return r;
}
// swish(x) = 0.5x*tanh(0.5x) + 0.5x   (packed, 1 MUFU per lane)
__device__ __forceinline__ ull swish2(ull x, ull h2) {
    ull t = mul2(x, h2);
    float a, b; unpack2(t, a, b);
    ull th = pack2(tanh_ap(a), tanh_ap(b));
    return fma2(t, th, t);
}

// ---------------- GEMM body: Y = X(Mx256) @ W(256x256) + bias ----------------
__device__ __forceinline__ void gemm_body(const float* __restrict__ X,
                                          const float* __restrict__ W,
                                          const float* __restrict__ bias,
                                          float* __restrict__ Y) {
    __shared__ float As[16][68];
    __shared__ float Bs[16][68];

    int t  = threadIdx.x;
    int tx = t & 15;
    int ty = t >> 4;
    int m0 = blockIdx.y * 64;
    int n0 = blockIdx.x * 64;

    float acc[4][4];
#pragma unroll
    for (int i = 0; i < 4; i++)
#pragma unroll
        for (int j = 0; j < 4; j++) acc[i][j] = 0.0f;

    for (int k0 = 0; k0 < Cc; k0 += 16) {
        {
            int r = t >> 2;
            int c = (t & 3) << 2;
            float4 v = *(const float4*)&X[(size_t)(m0 + r) * Cc + k0 + c];
            As[c + 0][r] = v.x; As[c + 1][r] = v.y;
            As[c + 2][r] = v.z; As[c + 3][r] = v.w;
        }
        {
            int r = t >> 4;
            int c = (t & 15) << 2;
            *(float4*)&Bs[r][c] = *(const float4*)&W[(size_t)(k0 + r) * Cc + n0 + c];
        }
        __syncthreads();
#pragma unroll
        for (int k = 0; k < 16; k++) {
            float a[4], b[4];
            *(float4*)a = *(const float4*)&As[k][ty << 2];
            *(float4*)b = *(const float4*)&Bs[k][tx << 2];
#pragma unroll
            for (int i = 0; i < 4; i++)
#pragma unroll
                for (int j = 0; j < 4; j++) acc[i][j] = fmaf(a[i], b[j], acc[i][j]);
        }
        __syncthreads();
    }

    float4 bv = *(const float4*)&bias[n0 + (tx << 2)];
#pragma unroll
    for (int i = 0; i < 4; i++) {
        float4 o;
        o.x = acc[i][0] + bv.x; o.y = acc[i][1] + bv.y;
        o.z = acc[i][2] + bv.z; o.w = acc[i][3] + bv.w;
        *(float4*)&Y[(size_t)(m0 + (ty << 2) + i) * Cc + n0 + (tx << 2)] = o;
    }
}

__global__ void gemm_qkv_kernel(const float* __restrict__ X,
                                const float* __restrict__ qw, const float* __restrict__ qb,
                                const float* __restrict__ kw, const float* __restrict__ kb,
                                const float* __restrict__ iw, const float* __restrict__ ib,
                                float* __restrict__ Qp, float* __restrict__ Kp,
                                float* __restrict__ Vp) {
    const float* W; const float* bias; float* Y;
    if (blockIdx.z == 0)      { W = qw; bias = qb; Y = Qp; }
    else if (blockIdx.z == 1) { W = kw; bias = kb; Y = Kp; }
    else                      { W = iw; bias = ib; Y = Vp; }
    gemm_body(X, W, bias, Y);
}

__global__ void gemm_out_kernel(const float* __restrict__ X,
                                const float* __restrict__ ow, const float* __restrict__ ob,
                                float* __restrict__ Yout) {
    gemm_body(X, ow, ob, Yout);
}

// ---------------- logits: pre[b][h][n][m] = A_loc + A_feat ----------------
// CTA: 16 n x 32 m tile, 128 threads.
// Thread (ni = t>>4 in 0..7, mg = t&15): rows 2ni, 2ni+1; m-pair m0+2mg (f32x2).
#define LOGITS_SMEM_BYTES (18768 * 4)

__global__ __launch_bounds__(128, 3)
void logits_kernel(const float* __restrict__ g,
                   const float* __restrict__ Q,
                   const float* __restrict__ K,
                   const float* __restrict__ w1, const float* __restrict__ b1,
                   const float* __restrict__ w2, const float* __restrict__ b2,
                   const float* __restrict__ w3, const float* __restrict__ b3,
                   float* __restrict__ pre) {
    extern __shared__ float sm[];
    float*  Qs  = sm;
    float*  Kt  = sm + 4160;
    float2* w1d = (float2*)(sm + 12352);
    float2* w2d = (float2*)(sm + 13888);
    float2* w3d = (float2*)(sm + 17984);
    float2* b1d = (float2*)(sm + 18240);
    float2* b2d = (float2*)(sm + 18496);
    float2* b3d = (float2*)(sm + 18752);

    int b  = blockIdx.z;
    int n0 = blockIdx.y * 16;
    int m0 = blockIdx.x * 32;
    int t  = threadIdx.x;

    // duplicated weights (cooperative, 128 threads)
#pragma unroll
    for (int i = t; i < Hh * DG * HID; i += 128) { float v = w1[i]; w1d[i] = make_float2(v, v); }
#pragma unroll
    for (int i = t; i < Hh * HID * HID; i += 128){ float v = w2[i]; w2d[i] = make_float2(v, v); }
    {
        float v = w3[t]; w3d[t] = make_float2(v, v);
        float u = b1[t]; b1d[t] = make_float2(u, u);
        float z = b2[t]; b2d[t] = make_float2(z, z);
    }
    if (t < Hh) { float v = b3[t]; b3d[t] = make_float2(v, v); }

    // Q tile [16 n][256 c]
    {
        int r = t >> 3, c = (t & 7) << 5;   // 32 floats per thread
        const float* src = Q + (size_t)(b * Nn + n0 + r) * Cc + c;
#pragma unroll
        for (int v = 0; v < 8; v++)
            *(float4*)&Qs[r * 260 + c + v * 4] = *(const float4*)(src + v * 4);
    }
    // K tile transposed: Kt[c][m] (4x4 register-block transpose, 4 blocks/thread)
#pragma unroll
    for (int bi = 0; bi < 4; bi++) {
        int blk = t + bi * 128;          // 0..511
        int bm = (blk & 7) << 2;
        int bc = (blk >> 3) << 2;
        const float* kp = K + (size_t)(b * Nn + m0 + bm) * Cc + bc;
        float4 r0 = *(const float4*)kp;
        float4 r1 = *(const float4*)(kp + Cc);
        float4 r2 = *(const float4*)(kp + 2 * Cc);
        float4 r3 = *(const float4*)(kp + 3 * Cc);
        *(float4*)&Kt[(bc + 0) * 32 + bm] = make_float4(r0.x, r1.x, r2.x, r3.x);
        *(float4*)&Kt[(bc + 1) * 32 + bm] = make_float4(r0.y, r1.y, r2.y, r3.y);
        *(float4*)&Kt[(bc + 2) * 32 + bm] = make_float4(r0.z, r1.z, r2.z, r3.z);
        *(float4*)&Kt[(bc + 3) * 32 + bm] = make_float4(r0.w, r1.w, r2.w, r3.w);
    }
    __syncthreads();

    int ni = t >> 4, mg = t & 15;
    int nr0 = n0 + 2 * ni;               // global row 0 (row 1 = +1)
    int m   = m0 + 2 * mg;

    // pairwise_g packed for both rows: g?[k] = {g[n][m][k], g[n][m+1][k]}
    ull ga[6], gb[6];
    {
        const float* gp0 = g + ((size_t)(b * Nn + nr0) * Nn + m) * DG;
        const float* gp1 = gp0 + (size_t)Nn * DG;
        float4 f0 = *(const float4*)gp0;
        float4 f1 = *(const float4*)(gp0 + 4);
        float4 f2 = *(const float4*)(gp0 + 8);
        ga[0] = pack2(f0.x, f1.z); ga[1] = pack2(f0.y, f1.w);
        ga[2] = pack2(f0.z, f2.x); ga[3] = pack2(f0.w, f2.y);
        ga[4] = pack2(f1.x, f2.z); ga[5] = pack2(f1.y, f2.w);
        float4 e0 = *(const float4*)gp1;
        float4 e1 = *(const float4*)(gp1 + 4);
        float4 e2 = *(const float4*)(gp1 + 8);
        gb[0] = pack2(e0.x, e1.z); gb[1] = pack2(e0.y, e1.w);
        gb[2] = pack2(e0.z, e2.x); gb[3] = pack2(e0.w, e2.y);
        gb[4] = pack2(e1.x, e2.z); gb[5] = pack2(e1.y, e2.w);
    }

    const ull h2 = pack2(0.5f, 0.5f);
    unsigned w1a = s2u(w1d), w2a = s2u(w2d), w3a = s2u(w3d);
    unsigned b1a = s2u(b1d), b2a = s2u(b2d), b3a = s2u(b3d);
    unsigned kta = s2u(Kt) + mg * 8;

#pragma unroll 1
    for (int h = 0; h < Hh; h++) {
        // ----- layer 1: 6 -> 16, both rows -----
        ull x0[16], x1[16];
        {
            unsigned ba = b1a + h * 128;
#pragma unroll
            for (int j = 0; j < 16; j += 2) {
                lds2u64(x0[j], x0[j + 1], ba + j * 8);
                x1[j] = x0[j]; x1[j + 1] = x0[j + 1];
            }
        }
#pragma unroll
        for (int k = 0; k < DG; k++) {
            unsigned wa = w1a + (h * DG + k) * 128;
#pragma unroll
            for (int j = 0; j < 16; j += 2) {
                ull wlo, whi; lds2u64(wlo, whi, wa + j * 8);
                x0[j]     = fma2(ga[k], wlo, x0[j]);
                x0[j + 1] = fma2(ga[k], whi, x0[j + 1]);
                x1[j]     = fma2(gb[k], wlo, x1[j]);
                x1[j + 1] = fma2(gb[k], whi, x1[j + 1]);
            }
        }
#pragma unroll
        for (int j = 0; j < 16; j++) { x0[j] = swish2(x0[j], h2); x1[j] = swish2(x1[j], h2); }

        // ----- layer 2 (in two j-halves) + layer 3 folded in -----
        ull a30 = lds1u64(b3a + h * 8);
        ull a31 = a30;
#pragma unroll
        for (int jh = 0; jh < 2; jh++) {
            ull y0[8], y1[8];
            unsigned ba = b2a + h * 128 + jh * 64;
#pragma unroll
            for (int j = 0; j < 8; j += 2) {
                lds2u64(y0[j], y0[j + 1], ba + j * 8);
                y1[j] = y0[j]; y1[j + 1] = y0[j + 1];
            }
#pragma unroll
            for (int k = 0; k < HID; k++) {
                unsigned wa = w2a + (h * HID + k) * 128 + jh * 64;
#pragma unroll
                for (int j = 0; j < 8; j += 2) {
                    ull wlo, whi; lds2u64(wlo, whi, wa + j * 8);
                    y0[j]     = fma2(x0[k], wlo, y0[j]);
                    y0[j + 1] = fma2(x0[k], whi, y0[j + 1]);
                    y1[j]     = fma2(x1[k], wlo, y1[j]);
                    y1[j + 1] = fma2(x1[k], whi, y1[j + 1]);
                }
            }
#pragma unroll
            for (int j = 0; j < 8; j++) { y0[j] = swish2(y0[j], h2); y1[j] = swish2(y1[j], h2); }
#pragma unroll
            for (int j = 0; j < 8; j += 2) {
                ull wlo, whi; lds2u64(wlo, whi, w3a + h * 128 + jh * 64 + j * 8);
                a30 = fma2(y0[j], wlo, a30); a30 = fma2(y0[j + 1], whi, a30);
                a31 = fma2(y1[j], wlo, a31); a31 = fma2(y1[j + 1], whi, a31);
            }
        }
        ull aloc0 = swish2(a30, h2);
        ull aloc1 = swish2(a31, h2);

        // ----- A_feat for both rows (K channels shared) -----
        ull af0 = pack2(0.0f, 0.0f), af1 = af0;
        unsigned kh = kta + (h * 32) * 128;
#pragma unroll
        for (int cc = 0; cc < 32; cc += 4) {
            float4 q0 = *(const float4*)&Qs[(2 * ni) * 260 + h * 32 + cc];
            float4 q1 = *(const float4*)&Qs[(2 * ni + 1) * 260 + h * 32 + cc];
            ull k0 = lds1u64(kh + (cc + 0) * 128);
            ull k1 = lds1u64(kh + (cc + 1) * 128);
            ull k2 = lds1u64(kh + (cc + 2) * 128);
            ull k3 = lds1u64(kh + (cc + 3) * 128);
            af0 = fma2(k0, pack2(q0.x, q0.x), af0);
            af0 = fma2(k1, pack2(q0.y, q0.y), af0);
            af0 = fma2(k2, pack2(q0.z, q0.z), af0);
            af0 = fma2(k3, pack2(q0.w, q0.w), af0);
            af1 = fma2(k0, pack2(q1.x, q1.x), af1);
            af1 = fma2(k1, pack2(q1.y, q1.y), af1);
            af1 = fma2(k2, pack2(q1.z, q1.z), af1);
            af1 = fma2(k3, pack2(q1.w, q1.w), af1);
        }

        float a0, a1, l0, l1;
        float* pr = pre + ((size_t)(b * Hh + h) * Nn + nr0) * Nn + m;
        unpack2(af0, a0, a1); unpack2(aloc0, l0, l1);
        *(float2*)pr = make_float2(l0 + a0 * 0.0625f, l1 + a1 * 0.0625f);
        unpack2(af1, a0, a1); unpack2(aloc1, l0, l1);
        *(float2*)(pr + Nn) = make_float2(l0 + a0 * 0.0625f, l1 + a1 * 0.0625f);
    }
}

// ---------------- softmax over m + att@V (256 threads, split-m AV) ----------------
// Phase A: thread (row = t>>4, l16 = t&15) loads 8 float4 of pre (masked),
//          row-max/sum via 16-lane shfl groups, exp stored to smem.
// Phase B: thread (row = t>>4, half = (t>>3)&1, dq = t&7) accumulates
//          out[row][dq*4..] over its 256-m half; halves combined in smem.
__global__ __launch_bounds__(256)
void softmax_av_kernel(const float* __restrict__ pre,
                       const float* __restrict__ V,
                       const int* __restrict__ mask,
                       float* __restrict__ out) {
    __shared__ float att[16][520];
    __shared__ float4 part[16][8];

    int b  = blockIdx.z;
    int h  = blockIdx.y;
    int n0 = blockIdx.x * 16;
    int t  = threadIdx.x;
    int row = t >> 4;
    int l16 = t & 15;

    const float4* prow = (const float4*)(pre + ((size_t)(b * Hh + h) * Nn + n0 + row) * Nn);
    const int4*   mk4  = (const int4*)(mask + b * Nn);

    // ---- load + mask + row max ----
    float4 buf[8];
    float mx = -3.0e38f;
#pragma unroll
    for (int j = 0; j < 8; j++) {
        int i4 = j * 16 + l16;        // float4 index 0..127
        float4 v = prow[i4];
        int4  mm = mk4[i4];
        v.x = mm.x ? v.x : -1e38f;
        v.y = mm.y ? v.y : -1e38f;
        v.z = mm.z ? v.z : -1e38f;
        v.w = mm.w ? v.w : -1e38f;
        buf[j] = v;
        mx = fmaxf(mx, fmaxf(fmaxf(v.x, v.y), fmaxf(v.z, v.w)));
    }
    mx = fmaxf(mx, __shfl_xor_sync(0xffffffff, mx, 1));
    mx = fmaxf(mx, __shfl_xor_sync(0xffffffff, mx, 2));
    mx = fmaxf(mx, __shfl_xor_sync(0xffffffff, mx, 4));
    mx = fmaxf(mx, __shfl_xor_sync(0xffffffff, mx, 8));

    // ---- exp + row sum; store e to smem ----
    float s = 0.0f;
#pragma unroll
    for (int j = 0; j < 8; j++) {
        int i4 = j * 16 + l16;
        float4 v = buf[j];
        float4 e;
        e.x = __expf(v.x - mx); e.y = __expf(v.y - mx);
        e.z = __expf(v.z - mx); e.w = __expf(v.w - mx);
        s += e.x + e.y + e.z + e.w;
        *(float4*)&att[row][i4 * 4] = e;
    }
    s += __shfl_xor_sync(0xffffffff, s, 1);
    s += __shfl_xor_sync(0xffffffff, s, 2);
    s += __shfl_xor_sync(0xffffffff, s, 4);
    s += __shfl_xor_sync(0xffffffff, s, 8);
    float invs = __fdividef(1.0f, s);

    __syncthreads();

    // ---- att @ V over this thread's m-half ----
    int half = (t >> 3) & 1;
    int dq   = t & 7;
    const float* vp = V + (size_t)b * Nn * Cc + h * Dd + (dq << 2);
    int mbase = half << 8;

    float4 acc = make_float4(0.f, 0.f, 0.f, 0.f);
#pragma unroll 2
    for (int mm = 0; mm < 256; mm += 4) {
        int m = mbase + mm;
        float4 a4 = *(const float4*)&att[row][m];
        float4 v0 = *(const float4*)(vp + (size_t)(m + 0) * Cc);
        float4 v1 = *(const float4*)(vp + (size_t)(m + 1) * Cc);
        float4 v2 = *(const float4*)(vp + (size_t)(m + 2) * Cc);
        float4 v3 = *(const float4*)(vp + (size_t)(m + 3) * Cc);
        acc.x = fmaf(a4.x, v0.x, acc.x); acc.y = fmaf(a4.x, v0.y, acc.y);
        acc.z = fmaf(a4.x, v0.z, acc.z); acc.w = fmaf(a4.x, v0.w, acc.w);
        acc.x = fmaf(a4.y, v1.x, acc.x); acc.y = fmaf(a4.y, v1.y, acc.y);
        acc.z = fmaf(a4.y, v1.z, acc.z); acc.w = fmaf(a4.y, v1.w, acc.w);
        acc.x = fmaf(a4.z, v2.x, acc.x); acc.y = fmaf(a4.z, v2.y, acc.y);
        acc.z = fmaf(a4.z, v2.z, acc.z); acc.w = fmaf(a4.z, v2.w, acc.w);
        acc.x = fmaf(a4.w, v3.x, acc.x); acc.y = fmaf(a4.w, v3.y, acc.y);
        acc.z = fmaf(a4.w, v3.z, acc.z); acc.w = fmaf(a4.w, v3.w, acc.w);
    }

    if (half == 1) part[row][dq] = acc;
    __syncthreads();

    if (half == 0) {
        float4 p = part[row][dq];
        acc.x = (acc.x + p.x) * invs;
        acc.y = (acc.y + p.y) * invs;
        acc.z = (acc.z + p.z) * invs;
        acc.w = (acc.w + p.w) * invs;
        *(float4*)&out[(size_t)(b * Nn + n0 + row) * Cc + h * Dd + (dq << 2)] = acc;
    }
}

// ---------------- launch ----------------
extern "C" void kernel_launch(void* const* d_in, const int* in_sizes, int n_in,
                              void* d_out, int out_size) {
    const float* pg = (const float*)d_in[0];
    const float* cs = (const float*)d_in[1];
    const float* qw = (const float*)d_in[2];
    const float* qb = (const float*)d_in[3];
    const float* kw = (const float*)d_in[4];
    const float* kb = (const float*)d_in[5];
    const float* iw = (const float*)d_in[6];
    const float* ib = (const float*)d_in[7];
    const float* ow = (const float*)d_in[8];
    const float* ob = (const float*)d_in[9];
    const float* w1 = (const float*)d_in[10];
    const float* b1 = (const float*)d_in[11];
    const float* w2 = (const float*)d_in[12];
    const float* b2 = (const float*)d_in[13];
    const float* w3 = (const float*)d_in[14];
    const float* b3 = (const float*)d_in[15];
    const int*  mask = (const int*)d_in[16];

    float *Qp, *Kp, *Vp, *Op, *Pp;
    cudaGetSymbolAddress((void**)&Qp, g_Q);
    cudaGetSymbolAddress((void**)&Kp, g_K);
    cudaGetSymbolAddress((void**)&Vp, g_V);
    cudaGetSymbolAddress((void**)&Op, g_O);
    cudaGetSymbolAddress((void**)&Pp, g_pre);

    cudaFuncSetAttribute(logits_kernel,
                         cudaFuncAttributeMaxDynamicSharedMemorySize,
                         LOGITS_SMEM_BYTES);

    const int M = Bn * Nn;   // 2048

    gemm_qkv_kernel<<<dim3(Cc / 64, M / 64, 3), 256>>>(cs, qw, qb, kw, kb, iw, ib,
                                                       Qp, Kp, Vp);

    logits_kernel<<<dim3(Nn / 32, Nn / 16, Bn), 128, LOGITS_SMEM_BYTES>>>(
        pg, Qp, Kp, w1, b1, w2, b2, w3, b3, Pp);

    softmax_av_kernel<<<dim3(Nn / 16, Hh, Bn), 256>>>(Pp, Vp, mask, Op);

    gemm_out_kernel<<<dim3(Cc / 64, M / 64), 256>>>(Op, ow, ob, (float*)d_out);
}